// round 16
// baseline (speedup 1.0000x reference)
#include <cuda_runtime.h>
#include <cuda_bf16.h>
#include <cuda_fp16.h>
#include <cstdint>

#define N_NODES  10000
#define BATCH    4
#define CIN      256
#define HC       512
#define NH       4
#define CH       128
#define E_EDGES  160000
#define E_TOT    170000
#define ROWS_TOT 40000

// ---------------- scratch (static device globals; no allocs) ----------------
__device__ __half d_xl16[(size_t)ROWS_TOT * HC];
__device__ float d_xr[(size_t)ROWS_TOT * HC];
__device__ __nv_bfloat16 d_hhi[(size_t)ROWS_TOT * CH];
__device__ __nv_bfloat16 d_hlo[(size_t)ROWS_TOT * CH];
__device__ __nv_bfloat16 d_xhi[(size_t)ROWS_TOT * CIN];
__device__ __nv_bfloat16 d_xlo[(size_t)ROWS_TOT * CIN];
__device__ __nv_bfloat16 d_whi[(size_t)1024 * CIN];   // [Wl;Wr]
__device__ __nv_bfloat16 d_wlo[(size_t)1024 * CIN];
__device__ __nv_bfloat16 d_fwhi[(size_t)CH * CH];
__device__ __nv_bfloat16 d_fwlo[(size_t)CH * CH];
__device__ int   d_deg[N_NODES];          // zero at load; scan re-zeroes each run
__device__ int   d_indptr[N_NODES + 1];
__device__ int   d_cursor[N_NODES];
__device__ int   d_csrc[E_TOT];

// ---------------- CSR setup (side stream) ------------------------------------
// per-thread dtype detection from first 8 int64 slots (L2-hot broadcast)
__device__ __forceinline__ int detect_is64(const void* ei) {
    const long long* p = (const long long*)ei;
    int ok = 1;
    #pragma unroll
    for (int i = 0; i < 8; i++) {
        long long v = p[i];
        if (v < 0 || v >= N_NODES) ok = 0;
    }
    return ok;
}
__device__ __forceinline__ int edge_at(const void* ei, int is64, int idx) {
    return is64 ? (int)((const long long*)ei)[idx] : ((const int*)ei)[idx];
}

__global__ void count_kernel(const void* __restrict__ ei) {
    int e = blockIdx.x * blockDim.x + threadIdx.x;
    if (e < E_EDGES) {
        int is64 = detect_is64(ei);
        atomicAdd(&d_deg[edge_at(ei, is64, E_EDGES + e)], 1);
    }
}

__global__ void scan_kernel() {   // indptr = prefix(deg + 1 self loop); zero deg
    __shared__ int wsum[32];
    int t = threadIdx.x, lane = t & 31, w = t >> 5;
    int local[10];
    int s = 0;
    #pragma unroll
    for (int i = 0; i < 10; i++) {
        int idx = t * 10 + i;
        local[i] = s;
        if (idx < N_NODES) {
            s += d_deg[idx] + 1;
            d_deg[idx] = 0;       // reset for next graph replay
        }
    }
    int v = s;
    #pragma unroll
    for (int off = 1; off < 32; off <<= 1) {
        int u = __shfl_up_sync(0xffffffffu, v, off);
        if (lane >= off) v += u;
    }
    if (lane == 31) wsum[w] = v;
    __syncthreads();
    if (w == 0) {
        int x = wsum[lane];
        #pragma unroll
        for (int off = 1; off < 32; off <<= 1) {
            int u = __shfl_up_sync(0xffffffffu, x, off);
            if (lane >= off) x += u;
        }
        wsum[lane] = x;
    }
    __syncthreads();
    int pre = (v - s) + ((w > 0) ? wsum[w - 1] : 0);
    #pragma unroll
    for (int i = 0; i < 10; i++) {
        int idx = t * 10 + i;
        if (idx < N_NODES) {
            int val = pre + local[i];
            d_indptr[idx] = val;
            d_cursor[idx] = val;
        }
    }
    if (t == 999) d_indptr[N_NODES] = pre + s;
}

__global__ void fill_kernel(const void* __restrict__ ei) {
    int e = blockIdx.x * blockDim.x + threadIdx.x;
    if (e >= E_TOT) return;
    int src, dst;
    if (e < E_EDGES) {
        int is64 = detect_is64(ei);
        src = edge_at(ei, is64, e);
        dst = edge_at(ei, is64, E_EDGES + e);
    } else {
        src = dst = e - E_EDGES;
    }
    d_csrc[atomicAdd(&d_cursor[dst], 1)] = src;
}

// ---------------- fp32 -> bf16 hi/lo conversion ------------------------------
__device__ __forceinline__ void cvt_store(__nv_bfloat16* hi, __nv_bfloat16* lo,
                                          size_t base, float4 v) {
    __nv_bfloat16 h0 = __float2bfloat16(v.x);
    __nv_bfloat16 h1 = __float2bfloat16(v.y);
    __nv_bfloat16 h2 = __float2bfloat16(v.z);
    __nv_bfloat16 h3 = __float2bfloat16(v.w);
    __nv_bfloat16 l0 = __float2bfloat16(v.x - __bfloat162float(h0));
    __nv_bfloat16 l1 = __float2bfloat16(v.y - __bfloat162float(h1));
    __nv_bfloat16 l2 = __float2bfloat16(v.z - __bfloat162float(h2));
    __nv_bfloat16 l3 = __float2bfloat16(v.w - __bfloat162float(h3));
    __nv_bfloat162 hp0 = {h0, h1}, hp1 = {h2, h3}, lp0 = {l0, l1}, lp1 = {l2, l3};
    *(uint2*)(hi + base) = make_uint2(*(uint32_t*)&hp0, *(uint32_t*)&hp1);
    *(uint2*)(lo + base) = make_uint2(*(uint32_t*)&lp0, *(uint32_t*)&lp1);
}

#define XN4  (ROWS_TOT * CIN / 4)
#define WN4H (512 * CIN / 4)
#define FW4  (CH * CH / 4)

__global__ void convert_kernel(const float* __restrict__ X,
                               const float* __restrict__ Wl,
                               const float* __restrict__ Wr,
                               const float* __restrict__ FW) {
    int idx = blockIdx.x * blockDim.x + threadIdx.x;
    if (idx < XN4) {
        cvt_store(d_xhi, d_xlo, (size_t)idx * 4, ((const float4*)X)[idx]);
    } else if (idx < XN4 + WN4H) {
        int w = idx - XN4;
        cvt_store(d_whi, d_wlo, (size_t)w * 4, ((const float4*)Wl)[w]);
    } else if (idx < XN4 + 2 * WN4H) {
        int w = idx - XN4 - WN4H;
        cvt_store(d_whi, d_wlo, (size_t)(512 * CIN) + (size_t)w * 4, ((const float4*)Wr)[w]);
    } else if (idx < XN4 + 2 * WN4H + FW4) {
        int w = idx - XN4 - 2 * WN4H;
        cvt_store(d_fwhi, d_fwlo, (size_t)w * 4, ((const float4*)FW)[w]);
    }
}

// ---------------- mma.sync / cp.async helpers --------------------------------
__device__ __forceinline__ uint32_t smem_u32(const void* p) {
    uint32_t a;
    asm("{ .reg .u64 t; cvta.to.shared.u64 t, %1; cvt.u32.u64 %0, t; }"
        : "=r"(a) : "l"(p));
    return a;
}

#define LDSM_X4(r0, r1, r2, r3, a) \
    asm volatile("ldmatrix.sync.aligned.m8n8.x4.shared.b16 {%0,%1,%2,%3}, [%4];" \
                 : "=r"(r0), "=r"(r1), "=r"(r2), "=r"(r3) : "r"(a))

#define MMA_BF16(d, a, b) \
    asm volatile("mma.sync.aligned.m16n8k16.row.col.f32.bf16.bf16.f32 " \
                 "{%0,%1,%2,%3}, {%4,%5,%6,%7}, {%8,%9}, {%0,%1,%2,%3};" \
                 : "+f"((d)[0]), "+f"((d)[1]), "+f"((d)[2]), "+f"((d)[3]) \
                 : "r"((a)[0]), "r"((a)[1]), "r"((a)[2]), "r"((a)[3]), \
                   "r"((b)[0]), "r"((b)[1]))

#define CP_ASYNC16(sa, gp) \
    asm volatile("cp.async.cg.shared.global [%0], [%1], 16;" :: "r"(sa), "l"(gp))
#define CP_COMMIT() asm volatile("cp.async.commit_group;" ::: "memory")
#define CP_WAIT(n)  asm volatile("cp.async.wait_group %0;" :: "n"(n) : "memory")

// ---------------- GEMM 1: [rows] x [1024,256]^T via HMMA ---------------------
// 2 CTAs/SM: CTA tile 128x128, 256 threads (4m x 2n warps, warp tile 32x64),
// K chunk 32 (80B padded rows), double-buffered cp.async. bf16 3-product.
#define RPB2  80
#define A_HI2 0
#define A_LO2 (128 * RPB2)
#define B_HI2 (2 * 128 * RPB2)
#define B_LO2 (3 * 128 * RPB2)
#define STAGE2 (4 * 128 * RPB2)        // 40960
#define SMEM_G1 (2 * STAGE2)           // 81920

__device__ __forceinline__ void g1_load_chunk(uint32_t stg, int tid,
                                              int row0, int row_limit,
                                              int colbase, int k0) {
    #pragma unroll
    for (int i = 0; i < 8; i++) {
        int idx = i * 256 + tid;
        int mat = idx >> 10;
        int buf = (idx >> 9) & 1;
        int r   = (idx >> 2) & 127;
        int g   = idx & 3;
        uint32_t sa = stg + (mat ? B_HI2 : A_HI2) + buf * (128 * RPB2)
                    + r * RPB2 + g * 16;
        const __nv_bfloat16* gp;
        if (mat == 0) {
            int arow = row0 + r; if (arow >= row_limit) arow = row_limit - 1;
            gp = (buf ? d_xlo : d_xhi) + (size_t)arow * CIN + k0 + g * 8;
        } else {
            gp = (buf ? d_wlo : d_whi) + (size_t)(colbase + r) * CIN + k0 + g * 8;
        }
        CP_ASYNC16(sa, gp);
    }
}

__global__ void __launch_bounds__(256, 2) gemm_xlr_mma(
    const float* __restrict__ bl, const float* __restrict__ br,
    int row_base, int row_limit)
{
    extern __shared__ char smem[];
    const uint32_t sbase = smem_u32(smem);

    const int tid  = threadIdx.x;
    const int wid  = tid >> 5;
    const int lane = tid & 31;
    const int warp_m = wid & 3;
    const int warp_n = wid >> 2;
    const int row0 = row_base + blockIdx.x * 128;
    const int col0 = blockIdx.y * 128;

    float acc[2][8][4];
    #pragma unroll
    for (int i = 0; i < 2; i++)
        #pragma unroll
        for (int j = 0; j < 8; j++)
            #pragma unroll
            for (int q = 0; q < 4; q++) acc[i][j][q] = 0.f;

    const int a_row  = warp_m * 32 + (lane & 15);
    const int a_koff = (lane >> 4) * 16;
    const int b_row  = warp_n * 64 + (lane >> 4) * 8 + (lane & 7);
    const int b_koff = ((lane >> 3) & 1) * 16;

    g1_load_chunk(sbase, tid, row0, row_limit, col0, 0);
    CP_COMMIT();

    #pragma unroll 1
    for (int c = 0; c < 8; c++) {
        const uint32_t stg = sbase + (c & 1) * STAGE2;
        if (c < 7) {
            g1_load_chunk(sbase + ((c + 1) & 1) * STAGE2, tid, row0, row_limit,
                          col0, (c + 1) * 32);
            CP_COMMIT();
            CP_WAIT(1);
        } else {
            CP_WAIT(0);
        }
        __syncthreads();

        #pragma unroll
        for (int ks = 0; ks < 2; ks++) {
            const int kb = ks * 32;
            uint32_t ahi[2][4], alo[2][4];
            #pragma unroll
            for (int mi = 0; mi < 2; mi++) {
                uint32_t ao = stg + (uint32_t)((a_row + mi * 16) * RPB2 + a_koff + kb);
                LDSM_X4(ahi[mi][0], ahi[mi][1], ahi[mi][2], ahi[mi][3], ao + A_HI2);
                LDSM_X4(alo[mi][0], alo[mi][1], alo[mi][2], alo[mi][3], ao + A_LO2);
            }
            uint32_t bhi[8][2], blo[8][2];
            #pragma unroll
            for (int p = 0; p < 4; p++) {
                uint32_t bo = stg + (uint32_t)((b_row + p * 16) * RPB2 + b_koff + kb);
                uint32_t t0, t1, t2, t3;
                LDSM_X4(t0, t1, t2, t3, bo + B_HI2);
                bhi[2 * p][0] = t0; bhi[2 * p][1] = t1;
                bhi[2 * p + 1][0] = t2; bhi[2 * p + 1][1] = t3;
                LDSM_X4(t0, t1, t2, t3, bo + B_LO2);
                blo[2 * p][0] = t0; blo[2 * p][1] = t1;
                blo[2 * p + 1][0] = t2; blo[2 * p + 1][1] = t3;
            }
            #pragma unroll
            for (int mi = 0; mi < 2; mi++)
                #pragma unroll
                for (int ni = 0; ni < 8; ni++) {
                    MMA_BF16(acc[mi][ni], ahi[mi], bhi[ni]);
                    MMA_BF16(acc[mi][ni], ahi[mi], blo[ni]);
                    MMA_BF16(acc[mi][ni], alo[mi], bhi[ni]);
                }
        }
        __syncthreads();
    }

    // epilogue: left half -> fp16 xl, right half -> fp32 xr
    const bool left = (col0 < 512);
    const float* bbase = left ? bl : br;
    const int wcolbase = (left ? col0 : (col0 - 512)) + warp_n * 64;
    const int lrow = lane >> 2;
    const int lcol = (lane & 3) * 2;
    #pragma unroll
    for (int mi = 0; mi < 2; mi++) {
        int gr0 = row0 + warp_m * 32 + mi * 16 + lrow;
        #pragma unroll
        for (int ni = 0; ni < 8; ni++) {
            int wc = wcolbase + ni * 8 + lcol;
            float b0 = bbase[wc], b1 = bbase[wc + 1];
            #pragma unroll
            for (int half_ = 0; half_ < 2; half_++) {
                int gr = gr0 + half_ * 8;
                if (gr >= row_limit) continue;
                float v0 = acc[mi][ni][half_ * 2 + 0] + b0;
                float v1 = acc[mi][ni][half_ * 2 + 1] + b1;
                if (left) {
                    __half2 hv = __floats2half2_rn(v0, v1);
                    *(__half2*)(d_xl16 + (size_t)gr * HC + wc) = hv;
                } else {
                    float2 v = {v0, v1};
                    *(float2*)(d_xr + (size_t)gr * HC + wc) = v;
                }
            }
        }
    }
}

// ---------------- edge/attention: warp/node, head-per-lane-group, 3-edge ILP
__device__ __forceinline__ void ld_xl16f(const __half* xl, float* v) {
    uint4 r0 = *(const uint4*)(xl);
    uint4 r1 = *(const uint4*)(xl + 8);
    const uint32_t* rw = (const uint32_t*)&r0;
    #pragma unroll
    for (int q = 0; q < 4; q++) {
        float2 f = __half22float2(*(__half2*)&rw[q]);
        v[q * 2] = f.x; v[q * 2 + 1] = f.y;
    }
    rw = (const uint32_t*)&r1;
    #pragma unroll
    for (int q = 0; q < 4; q++) {
        float2 f = __half22float2(*(__half2*)&rw[q]);
        v[8 + q * 2] = f.x; v[8 + q * 2 + 1] = f.y;
    }
}

__global__ void __launch_bounds__(256) gat_edge_kernel(
    const float* __restrict__ att, const float* __restrict__ gat_bias,
    int batch_base)
{
    const int b    = batch_base + blockIdx.y;
    const int node = blockIdx.x * 8 + (threadIdx.x >> 5);
    const int lane = threadIdx.x & 31;
    const int h    = lane >> 3;
    const int l8   = lane & 7;
    const int eoff = h * CH + l8 * 16;

    const size_t bb = (size_t)b * N_NODES;

    float xrr[16], attr[16];
    {
        const float* xrp = d_xr + (bb + node) * HC + eoff;
        const float* atp = att + eoff;
        #pragma unroll
        for (int q = 0; q < 4; q++) {
            float4 a = *(const float4*)(xrp + q * 4);
            xrr[q * 4] = a.x; xrr[q * 4 + 1] = a.y; xrr[q * 4 + 2] = a.z; xrr[q * 4 + 3] = a.w;
            float4 t = *(const float4*)(atp + q * 4);
            attr[q * 4] = t.x; attr[q * 4 + 1] = t.y; attr[q * 4 + 2] = t.z; attr[q * 4 + 3] = t.w;
        }
    }

    float m = -1e30f, s = 0.f;
    float acc[16];
    #pragma unroll
    for (int i = 0; i < 16; i++) acc[i] = 0.f;

    int beg = d_indptr[node], end = d_indptr[node + 1];
    int e = beg;

    for (; e + 2 < end; e += 3) {
        int s0 = d_csrc[e], s1 = d_csrc[e + 1], s2 = d_csrc[e + 2];
        float xv0[16], xv1[16], xv2[16];
        ld_xl16f(d_xl16 + (bb + s0) * HC + eoff, xv0);
        ld_xl16f(d_xl16 + (bb + s1) * HC + eoff, xv1);
        ld_xl16f(d_xl16 + (bb + s2) * HC + eoff, xv2);
        float p0 = 0.f, p1 = 0.f, p2 = 0.f;
        #pragma unroll
        for (int i = 0; i < 16; i++) {
            float e0 = xv0[i] + xrr[i]; e0 = fmaxf(e0, 0.2f * e0);
            float e1 = xv1[i] + xrr[i]; e1 = fmaxf(e1, 0.2f * e1);
            float e2 = xv2[i] + xrr[i]; e2 = fmaxf(e2, 0.2f * e2);
            p0 = fmaf(e0, attr[i], p0);
            p1 = fmaf(e1, attr[i], p1);
            p2 = fmaf(e2, attr[i], p2);
        }
        #pragma unroll
        for (int off = 4; off > 0; off >>= 1) {
            p0 += __shfl_xor_sync(0xffffffffu, p0, off);
            p1 += __shfl_xor_sync(0xffffffffu, p1, off);
            p2 += __shfl_xor_sync(0xffffffffu, p2, off);
        }
        float nm = fmaxf(fmaxf(m, p0), fmaxf(p1, p2));
        float sc = __expf(m - nm);
        float w0 = __expf(p0 - nm);
        float w1 = __expf(p1 - nm);
        float w2 = __expf(p2 - nm);
        s = fmaf(s, sc, w0 + w1 + w2);
        #pragma unroll
        for (int i = 0; i < 16; i++)
            acc[i] = fmaf(acc[i], sc,
                          fmaf(w0, xv0[i], fmaf(w1, xv1[i], w2 * xv2[i])));
        m = nm;
    }
    for (; e < end; e++) {
        int s0 = d_csrc[e];
        float xv0[16];
        ld_xl16f(d_xl16 + (bb + s0) * HC + eoff, xv0);
        float p0 = 0.f;
        #pragma unroll
        for (int i = 0; i < 16; i++) {
            float e0 = xv0[i] + xrr[i]; e0 = fmaxf(e0, 0.2f * e0);
            p0 = fmaf(e0, attr[i], p0);
        }
        #pragma unroll
        for (int off = 4; off > 0; off >>= 1)
            p0 += __shfl_xor_sync(0xffffffffu, p0, off);
        float nm = fmaxf(m, p0);
        float sc = __expf(m - nm);
        float w0 = __expf(p0 - nm);
        s = fmaf(s, sc, w0);
        #pragma unroll
        for (int i = 0; i < 16; i++)
            acc[i] = fmaf(acc[i], sc, w0 * xv0[i]);
        m = nm;
    }

    float r = 0.25f / s;
    float o[16];
    #pragma unroll
    for (int i = 0; i < 16; i++) {
        float v = acc[i] * r;
        v += __shfl_xor_sync(0xffffffffu, v, 8);
        v += __shfl_xor_sync(0xffffffffu, v, 16);
        o[i] = v;
    }

    if (h == 0) {
        size_t base = (bb + node) * CH + l8 * 16;
        #pragma unroll
        for (int q = 0; q < 4; q++) {
            float4 gv = *(const float4*)(gat_bias + l8 * 16 + q * 4);
            float4 v;
            v.x = o[q * 4 + 0] + gv.x;
            v.y = o[q * 4 + 1] + gv.y;
            v.z = o[q * 4 + 2] + gv.z;
            v.w = o[q * 4 + 3] + gv.w;
            cvt_store(d_hhi, d_hlo, base + q * 4, v);
        }
    }
}

// ---------------- GEMM 2 via HMMA: out = relu(h @ fc_w^T + fc_b) -------------
#define KPB   144
#define FC_A   0
#define FC_AL  (128 * KPB)
#define FC_B   (2 * 128 * KPB)
#define FC_BL  (3 * 128 * KPB)
#define SMEM_FC (4 * 128 * KPB)   // 73728

__global__ void __launch_bounds__(256) gemm_fc_mma(
    const float* __restrict__ bias, float* __restrict__ out)
{
    extern __shared__ char smem[];
    const uint32_t sbase = smem_u32(smem);
    const int tid  = threadIdx.x;
    const int wid  = tid >> 5;
    const int lane = tid & 31;
    const int warp_m = wid & 3;
    const int warp_n = wid >> 2;
    const int row0 = blockIdx.x * 128;

    float acc[2][8][4];
    #pragma unroll
    for (int i = 0; i < 2; i++)
        #pragma unroll
        for (int j = 0; j < 8; j++)
            #pragma unroll
            for (int q = 0; q < 4; q++) acc[i][j][q] = 0.f;

    const int a_row  = warp_m * 32 + (lane & 15);
    const int a_koff = (lane >> 4) * 16;
    const int b_row  = warp_n * 64 + (lane >> 4) * 8 + (lane & 7);
    const int b_koff = ((lane >> 3) & 1) * 16;

    #pragma unroll 1
    for (int c = 0; c < 2; c++) {
        const int k0 = c * 64;
        #pragma unroll
        for (int i = 0; i < 4; i++) {
            int idx = i * 256 + tid;
            int r = idx >> 3, g = idx & 7;
            uint32_t soff = (uint32_t)(r * KPB + g * 16);
            int grow = row0 + r; if (grow >= ROWS_TOT) grow = ROWS_TOT - 1;
            size_t aoff = (size_t)grow * CH + k0 + g * 8;
            size_t boff = (size_t)r * CH + k0 + g * 8;
            CP_ASYNC16(sbase + FC_A  + soff, d_hhi  + aoff);
            CP_ASYNC16(sbase + FC_AL + soff, d_hlo  + aoff);
            CP_ASYNC16(sbase + FC_B  + soff, d_fwhi + boff);
            CP_ASYNC16(sbase + FC_BL + soff, d_fwlo + boff);
        }
        CP_COMMIT();
        CP_WAIT(0);
        __syncthreads();

        #pragma unroll
        for (int ks = 0; ks < 4; ks++) {
            const int kb = ks * 32;
            uint32_t ahi[2][4], alo[2][4], bhi[8][2], blo[8][2];
            #pragma unroll
            for (int mi = 0; mi < 2; mi++) {
                uint32_t ao = sbase + (uint32_t)((a_row + mi * 16) * KPB + a_koff + kb);
                LDSM_X4(ahi[mi][0], ahi[mi][1], ahi[mi][2], ahi[mi][3], ao + FC_A);
                LDSM_X4(alo[mi][0], alo[mi][1], alo[mi][2], alo[mi][3], ao + FC_AL);
            }
            #pragma unroll
            for (int p = 0; p < 4; p++) {
                uint32_t bo = sbase + (uint32_t)((b_row + p * 16) * KPB + b_koff + kb);
                uint32_t t0, t1, t2, t3;
                LDSM_X4(t0, t1, t2, t3, bo + FC_B);
                bhi[2 * p][0] = t0; bhi[2 * p][1] = t1;
                bhi[2 * p + 1][0] = t2; bhi[2 * p + 1][1] = t3;
                LDSM_X4(t0, t1, t2, t3, bo + FC_BL);
                blo[2 * p][0] = t0; blo[2 * p][1] = t1;
                blo[2 * p + 1][0] = t2; blo[2 * p + 1][1] = t3;
            }
            #pragma unroll
            for (int mi = 0; mi < 2; mi++)
                #pragma unroll
                for (int ni = 0; ni < 8; ni++) {
                    MMA_BF16(acc[mi][ni], ahi[mi], bhi[ni]);
                    MMA_BF16(acc[mi][ni], ahi[mi], blo[ni]);
                    MMA_BF16(acc[mi][ni], alo[mi], bhi[ni]);
                }
        }
        __syncthreads();
    }

    const int wcolbase = warp_n * 64;
    const int lrow = lane >> 2;
    const int lcol = (lane & 3) * 2;
    #pragma unroll
    for (int mi = 0; mi < 2; mi++) {
        int gr0 = row0 + warp_m * 32 + mi * 16 + lrow;
        #pragma unroll
        for (int ni = 0; ni < 8; ni++) {
            int wc = wcolbase + ni * 8 + lcol;
            float b0 = bias[wc], b1 = bias[wc + 1];
            if (gr0 < ROWS_TOT) {
                float2 v = {fmaxf(acc[mi][ni][0] + b0, 0.f),
                            fmaxf(acc[mi][ni][1] + b1, 0.f)};
                *(float2*)(out + (size_t)gr0 * CH + wc) = v;
            }
            if (gr0 + 8 < ROWS_TOT) {
                float2 v = {fmaxf(acc[mi][ni][2] + b0, 0.f),
                            fmaxf(acc[mi][ni][3] + b1, 0.f)};
                *(float2*)(out + (size_t)(gr0 + 8) * CH + wc) = v;
            }
        }
    }
}

// ---------------- launch -----------------------------------------------------
extern "C" void kernel_launch(void* const* d_in, const int* in_sizes, int n_in,
                              void* d_out, int out_size)
{
    const float* x   = (const float*)d_in[0];
    const void*  ei  = d_in[1];
    const float* Wl  = (const float*)d_in[2];
    const float* bl  = (const float*)d_in[3];
    const float* Wr  = (const float*)d_in[4];
    const float* br  = (const float*)d_in[5];
    const float* att = (const float*)d_in[6];
    const float* gb  = (const float*)d_in[7];
    const float* fcw = (const float*)d_in[8];
    const float* fcb = (const float*)d_in[9];

    static int configured = 0;
    static cudaStream_t s_side;
    static cudaEvent_t ev_fork, ev_csr, ev_g0, ev_gat01;
    if (!configured) {
        cudaFuncSetAttribute(gemm_xlr_mma,
                             cudaFuncAttributeMaxDynamicSharedMemorySize, SMEM_G1);
        cudaFuncSetAttribute(gemm_fc_mma,
                             cudaFuncAttributeMaxDynamicSharedMemorySize, SMEM_FC);
        cudaStreamCreateWithFlags(&s_side, cudaStreamNonBlocking);
        cudaEventCreateWithFlags(&ev_fork, cudaEventDisableTiming);
        cudaEventCreateWithFlags(&ev_csr, cudaEventDisableTiming);
        cudaEventCreateWithFlags(&ev_g0, cudaEventDisableTiming);
        cudaEventCreateWithFlags(&ev_gat01, cudaEventDisableTiming);
        configured = 1;
    }

    const int HALF_ROWS = ROWS_TOT / 2;          // 20000 (batches 0,1 / 2,3)
    const int GX_HALF   = (HALF_ROWS + 127) / 128;  // 157

    // fork: CSR chain on side stream
    cudaEventRecord(ev_fork, 0);
    cudaStreamWaitEvent(s_side, ev_fork, 0);
    count_kernel<<<(E_EDGES + 255) / 256, 256, 0, s_side>>>(ei);
    scan_kernel<<<1, 1024, 0, s_side>>>();
    fill_kernel<<<(E_TOT + 255) / 256, 256, 0, s_side>>>(ei);
    cudaEventRecord(ev_csr, s_side);

    // main: convert + gemm1 half 0 (batches 0,1)
    const int cvt_tot = XN4 + 2 * WN4H + FW4;
    convert_kernel<<<(cvt_tot + 255) / 256, 256>>>(x, Wl, Wr, fcw);
    gemm_xlr_mma<<<dim3(GX_HALF, 8), 256, SMEM_G1>>>(bl, br, 0, HALF_ROWS);
    cudaEventRecord(ev_g0, 0);

    // main: gemm1 half 1 (batches 2,3)
    gemm_xlr_mma<<<dim3(GX_HALF, 8), 256, SMEM_G1>>>(bl, br, HALF_ROWS, ROWS_TOT);

    // side: gat batches 0,1 overlapped with gemm half 1 (CSR already ordered)
    cudaStreamWaitEvent(s_side, ev_g0, 0);
    gat_edge_kernel<<<dim3(N_NODES / 8, 2), 256, 0, s_side>>>(att, gb, 0);
    cudaEventRecord(ev_gat01, s_side);

    // main: gat batches 2,3 (after CSR), then fc after both gats
    cudaStreamWaitEvent(0, ev_csr, 0);
    gat_edge_kernel<<<dim3(N_NODES / 8, 2), 256>>>(att, gb, 2);
    cudaStreamWaitEvent(0, ev_gat01, 0);
    gemm_fc_mma<<<(ROWS_TOT + 127) / 128, 256, SMEM_FC>>>(fcb, (float*)d_out);
}

// round 17
// speedup vs baseline: 1.0415x; 1.0415x over previous
#include <cuda_runtime.h>
#include <cuda_bf16.h>
#include <cuda_fp16.h>
#include <cstdint>

#define N_NODES  10000
#define BATCH    4
#define CIN      256
#define HC       512
#define NH       4
#define CH       128
#define E_EDGES  160000
#define E_TOT    170000
#define ROWS_TOT 40000

// ---------------- scratch (static device globals; no allocs) ----------------
__device__ __half d_xl16[(size_t)ROWS_TOT * HC];
__device__ __half d_xr16[(size_t)ROWS_TOT * HC];
__device__ __nv_bfloat16 d_hhi[(size_t)ROWS_TOT * CH];
__device__ __nv_bfloat16 d_hlo[(size_t)ROWS_TOT * CH];
__device__ __nv_bfloat16 d_xhi[(size_t)ROWS_TOT * CIN];
__device__ __nv_bfloat16 d_xlo[(size_t)ROWS_TOT * CIN];
__device__ __nv_bfloat16 d_whi[(size_t)1024 * CIN];   // [Wl;Wr]
__device__ __nv_bfloat16 d_wlo[(size_t)1024 * CIN];
__device__ __nv_bfloat16 d_fwhi[(size_t)CH * CH];
__device__ __nv_bfloat16 d_fwlo[(size_t)CH * CH];
__device__ int   d_deg[N_NODES];          // zero at load; scan re-zeroes each run
__device__ int   d_indptr[N_NODES + 1];
__device__ int   d_cursor[N_NODES];
__device__ int   d_csrc[E_TOT];

// ---------------- CSR setup (side stream) ------------------------------------
__device__ __forceinline__ int detect_is64(const void* ei) {
    const long long* p = (const long long*)ei;
    int ok = 1;
    #pragma unroll
    for (int i = 0; i < 8; i++) {
        long long v = p[i];
        if (v < 0 || v >= N_NODES) ok = 0;
    }
    return ok;
}
__device__ __forceinline__ int edge_at(const void* ei, int is64, int idx) {
    return is64 ? (int)((const long long*)ei)[idx] : ((const int*)ei)[idx];
}

__global__ void count_kernel(const void* __restrict__ ei) {
    int e = blockIdx.x * blockDim.x + threadIdx.x;
    if (e < E_EDGES) {
        int is64 = detect_is64(ei);
        atomicAdd(&d_deg[edge_at(ei, is64, E_EDGES + e)], 1);
    }
}

__global__ void scan_kernel() {   // indptr = prefix(deg + 1 self loop); zero deg
    __shared__ int wsum[32];
    int t = threadIdx.x, lane = t & 31, w = t >> 5;
    int local[10];
    int s = 0;
    #pragma unroll
    for (int i = 0; i < 10; i++) {
        int idx = t * 10 + i;
        local[i] = s;
        if (idx < N_NODES) {
            s += d_deg[idx] + 1;
            d_deg[idx] = 0;
        }
    }
    int v = s;
    #pragma unroll
    for (int off = 1; off < 32; off <<= 1) {
        int u = __shfl_up_sync(0xffffffffu, v, off);
        if (lane >= off) v += u;
    }
    if (lane == 31) wsum[w] = v;
    __syncthreads();
    if (w == 0) {
        int x = wsum[lane];
        #pragma unroll
        for (int off = 1; off < 32; off <<= 1) {
            int u = __shfl_up_sync(0xffffffffu, x, off);
            if (lane >= off) x += u;
        }
        wsum[lane] = x;
    }
    __syncthreads();
    int pre = (v - s) + ((w > 0) ? wsum[w - 1] : 0);
    #pragma unroll
    for (int i = 0; i < 10; i++) {
        int idx = t * 10 + i;
        if (idx < N_NODES) {
            int val = pre + local[i];
            d_indptr[idx] = val;
            d_cursor[idx] = val;
        }
    }
    if (t == 999) d_indptr[N_NODES] = pre + s;
}

__global__ void fill_kernel(const void* __restrict__ ei) {
    int e = blockIdx.x * blockDim.x + threadIdx.x;
    if (e >= E_TOT) return;
    int src, dst;
    if (e < E_EDGES) {
        int is64 = detect_is64(ei);
        src = edge_at(ei, is64, e);
        dst = edge_at(ei, is64, E_EDGES + e);
    } else {
        src = dst = e - E_EDGES;
    }
    d_csrc[atomicAdd(&d_cursor[dst], 1)] = src;
}

// ---------------- fp32 -> bf16 hi/lo conversion ------------------------------
__device__ __forceinline__ void cvt_store(__nv_bfloat16* hi, __nv_bfloat16* lo,
                                          size_t base, float4 v) {
    __nv_bfloat16 h0 = __float2bfloat16(v.x);
    __nv_bfloat16 h1 = __float2bfloat16(v.y);
    __nv_bfloat16 h2 = __float2bfloat16(v.z);
    __nv_bfloat16 h3 = __float2bfloat16(v.w);
    __nv_bfloat16 l0 = __float2bfloat16(v.x - __bfloat162float(h0));
    __nv_bfloat16 l1 = __float2bfloat16(v.y - __bfloat162float(h1));
    __nv_bfloat16 l2 = __float2bfloat16(v.z - __bfloat162float(h2));
    __nv_bfloat16 l3 = __float2bfloat16(v.w - __bfloat162float(h3));
    __nv_bfloat162 hp0 = {h0, h1}, hp1 = {h2, h3}, lp0 = {l0, l1}, lp1 = {l2, l3};
    *(uint2*)(hi + base) = make_uint2(*(uint32_t*)&hp0, *(uint32_t*)&hp1);
    *(uint2*)(lo + base) = make_uint2(*(uint32_t*)&lp0, *(uint32_t*)&lp1);
}

#define XN4  (ROWS_TOT * CIN / 4)
#define WN4H (512 * CIN / 4)
#define FW4  (CH * CH / 4)

__global__ void convert_kernel(const float* __restrict__ X,
                               const float* __restrict__ Wl,
                               const float* __restrict__ Wr,
                               const float* __restrict__ FW) {
    int idx = blockIdx.x * blockDim.x + threadIdx.x;
    if (idx < XN4) {
        cvt_store(d_xhi, d_xlo, (size_t)idx * 4, ((const float4*)X)[idx]);
    } else if (idx < XN4 + WN4H) {
        int w = idx - XN4;
        cvt_store(d_whi, d_wlo, (size_t)w * 4, ((const float4*)Wl)[w]);
    } else if (idx < XN4 + 2 * WN4H) {
        int w = idx - XN4 - WN4H;
        cvt_store(d_whi, d_wlo, (size_t)(512 * CIN) + (size_t)w * 4, ((const float4*)Wr)[w]);
    } else if (idx < XN4 + 2 * WN4H + FW4) {
        int w = idx - XN4 - 2 * WN4H;
        cvt_store(d_fwhi, d_fwlo, (size_t)w * 4, ((const float4*)FW)[w]);
    }
}

// ---------------- mma.sync / cp.async helpers --------------------------------
__device__ __forceinline__ uint32_t smem_u32(const void* p) {
    uint32_t a;
    asm("{ .reg .u64 t; cvta.to.shared.u64 t, %1; cvt.u32.u64 %0, t; }"
        : "=r"(a) : "l"(p));
    return a;
}

#define LDSM_X4(r0, r1, r2, r3, a) \
    asm volatile("ldmatrix.sync.aligned.m8n8.x4.shared.b16 {%0,%1,%2,%3}, [%4];" \
                 : "=r"(r0), "=r"(r1), "=r"(r2), "=r"(r3) : "r"(a))

#define MMA_BF16(d, a, b) \
    asm volatile("mma.sync.aligned.m16n8k16.row.col.f32.bf16.bf16.f32 " \
                 "{%0,%1,%2,%3}, {%4,%5,%6,%7}, {%8,%9}, {%0,%1,%2,%3};" \
                 : "+f"((d)[0]), "+f"((d)[1]), "+f"((d)[2]), "+f"((d)[3]) \
                 : "r"((a)[0]), "r"((a)[1]), "r"((a)[2]), "r"((a)[3]), \
                   "r"((b)[0]), "r"((b)[1]))

#define CP_ASYNC16(sa, gp) \
    asm volatile("cp.async.cg.shared.global [%0], [%1], 16;" :: "r"(sa), "l"(gp))
#define CP_COMMIT() asm volatile("cp.async.commit_group;" ::: "memory")
#define CP_WAIT(n)  asm volatile("cp.async.wait_group %0;" :: "n"(n) : "memory")

// ---------------- GEMM 1: [rows] x [1024,256]^T via HMMA ---------------------
#define RPB2  80
#define A_HI2 0
#define A_LO2 (128 * RPB2)
#define B_HI2 (2 * 128 * RPB2)
#define B_LO2 (3 * 128 * RPB2)
#define STAGE2 (4 * 128 * RPB2)        // 40960
#define SMEM_G1 (2 * STAGE2)           // 81920

__device__ __forceinline__ void g1_load_chunk(uint32_t stg, int tid,
                                              int row0, int row_limit,
                                              int colbase, int k0) {
    #pragma unroll
    for (int i = 0; i < 8; i++) {
        int idx = i * 256 + tid;
        int mat = idx >> 10;
        int buf = (idx >> 9) & 1;
        int r   = (idx >> 2) & 127;
        int g   = idx & 3;
        uint32_t sa = stg + (mat ? B_HI2 : A_HI2) + buf * (128 * RPB2)
                    + r * RPB2 + g * 16;
        const __nv_bfloat16* gp;
        if (mat == 0) {
            int arow = row0 + r; if (arow >= row_limit) arow = row_limit - 1;
            gp = (buf ? d_xlo : d_xhi) + (size_t)arow * CIN + k0 + g * 8;
        } else {
            gp = (buf ? d_wlo : d_whi) + (size_t)(colbase + r) * CIN + k0 + g * 8;
        }
        CP_ASYNC16(sa, gp);
    }
}

__global__ void __launch_bounds__(256, 2) gemm_xlr_mma(
    const float* __restrict__ bl, const float* __restrict__ br,
    int row_base, int row_limit)
{
    extern __shared__ char smem[];
    const uint32_t sbase = smem_u32(smem);

    const int tid  = threadIdx.x;
    const int wid  = tid >> 5;
    const int lane = tid & 31;
    const int warp_m = wid & 3;
    const int warp_n = wid >> 2;
    const int row0 = row_base + blockIdx.x * 128;
    const int col0 = blockIdx.y * 128;

    float acc[2][8][4];
    #pragma unroll
    for (int i = 0; i < 2; i++)
        #pragma unroll
        for (int j = 0; j < 8; j++)
            #pragma unroll
            for (int q = 0; q < 4; q++) acc[i][j][q] = 0.f;

    const int a_row  = warp_m * 32 + (lane & 15);
    const int a_koff = (lane >> 4) * 16;
    const int b_row  = warp_n * 64 + (lane >> 4) * 8 + (lane & 7);
    const int b_koff = ((lane >> 3) & 1) * 16;

    g1_load_chunk(sbase, tid, row0, row_limit, col0, 0);
    CP_COMMIT();

    #pragma unroll 1
    for (int c = 0; c < 8; c++) {
        const uint32_t stg = sbase + (c & 1) * STAGE2;
        if (c < 7) {
            g1_load_chunk(sbase + ((c + 1) & 1) * STAGE2, tid, row0, row_limit,
                          col0, (c + 1) * 32);
            CP_COMMIT();
            CP_WAIT(1);
        } else {
            CP_WAIT(0);
        }
        __syncthreads();

        #pragma unroll
        for (int ks = 0; ks < 2; ks++) {
            const int kb = ks * 32;
            uint32_t ahi[2][4], alo[2][4];
            #pragma unroll
            for (int mi = 0; mi < 2; mi++) {
                uint32_t ao = stg + (uint32_t)((a_row + mi * 16) * RPB2 + a_koff + kb);
                LDSM_X4(ahi[mi][0], ahi[mi][1], ahi[mi][2], ahi[mi][3], ao + A_HI2);
                LDSM_X4(alo[mi][0], alo[mi][1], alo[mi][2], alo[mi][3], ao + A_LO2);
            }
            uint32_t bhi[8][2], blo[8][2];
            #pragma unroll
            for (int p = 0; p < 4; p++) {
                uint32_t bo = stg + (uint32_t)((b_row + p * 16) * RPB2 + b_koff + kb);
                uint32_t t0, t1, t2, t3;
                LDSM_X4(t0, t1, t2, t3, bo + B_HI2);
                bhi[2 * p][0] = t0; bhi[2 * p][1] = t1;
                bhi[2 * p + 1][0] = t2; bhi[2 * p + 1][1] = t3;
                LDSM_X4(t0, t1, t2, t3, bo + B_LO2);
                blo[2 * p][0] = t0; blo[2 * p][1] = t1;
                blo[2 * p + 1][0] = t2; blo[2 * p + 1][1] = t3;
            }
            #pragma unroll
            for (int mi = 0; mi < 2; mi++)
                #pragma unroll
                for (int ni = 0; ni < 8; ni++) {
                    MMA_BF16(acc[mi][ni], ahi[mi], bhi[ni]);
                    MMA_BF16(acc[mi][ni], ahi[mi], blo[ni]);
                    MMA_BF16(acc[mi][ni], alo[mi], bhi[ni]);
                }
        }
        __syncthreads();
    }

    // epilogue: fp16 stores (left -> xl, right -> xr)
    const bool left = (col0 < 512);
    const float* bbase = left ? bl : br;
    __half* outb = left ? d_xl16 : d_xr16;
    const int wcolbase = (left ? col0 : (col0 - 512)) + warp_n * 64;
    const int lrow = lane >> 2;
    const int lcol = (lane & 3) * 2;
    #pragma unroll
    for (int mi = 0; mi < 2; mi++) {
        int gr0 = row0 + warp_m * 32 + mi * 16 + lrow;
        #pragma unroll
        for (int ni = 0; ni < 8; ni++) {
            int wc = wcolbase + ni * 8 + lcol;
            float b0 = bbase[wc], b1 = bbase[wc + 1];
            #pragma unroll
            for (int half_ = 0; half_ < 2; half_++) {
                int gr = gr0 + half_ * 8;
                if (gr >= row_limit) continue;
                float v0 = acc[mi][ni][half_ * 2 + 0] + b0;
                float v1 = acc[mi][ni][half_ * 2 + 1] + b1;
                __half2 hv = __floats2half2_rn(v0, v1);
                *(__half2*)(outb + (size_t)gr * HC + wc) = hv;
            }
        }
    }
}

// ---------------- edge/attention: warp/node, head-per-lane-group, 3-edge ILP
__device__ __forceinline__ void ld_xl16f(const __half* xl, float* v) {
    uint4 r0 = *(const uint4*)(xl);
    uint4 r1 = *(const uint4*)(xl + 8);
    const uint32_t* rw = (const uint32_t*)&r0;
    #pragma unroll
    for (int q = 0; q < 4; q++) {
        float2 f = __half22float2(*(__half2*)&rw[q]);
        v[q * 2] = f.x; v[q * 2 + 1] = f.y;
    }
    rw = (const uint32_t*)&r1;
    #pragma unroll
    for (int q = 0; q < 4; q++) {
        float2 f = __half22float2(*(__half2*)&rw[q]);
        v[8 + q * 2] = f.x; v[8 + q * 2 + 1] = f.y;
    }
}

__global__ void __launch_bounds__(256) gat_edge_kernel(
    const float* __restrict__ att, const float* __restrict__ gat_bias,
    int batch_base)
{
    const int b    = batch_base + blockIdx.y;
    const int node = blockIdx.x * 8 + (threadIdx.x >> 5);
    const int lane = threadIdx.x & 31;
    const int h    = lane >> 3;
    const int l8   = lane & 7;
    const int eoff = h * CH + l8 * 16;

    const size_t bb = (size_t)b * N_NODES;

    float xrr[16], attr[16];
    ld_xl16f(d_xr16 + (bb + node) * HC + eoff, xrr);
    {
        const float* atp = att + eoff;
        #pragma unroll
        for (int q = 0; q < 4; q++) {
            float4 t = *(const float4*)(atp + q * 4);
            attr[q * 4] = t.x; attr[q * 4 + 1] = t.y; attr[q * 4 + 2] = t.z; attr[q * 4 + 3] = t.w;
        }
    }

    float m = -1e30f, s = 0.f;
    float acc[16];
    #pragma unroll
    for (int i = 0; i < 16; i++) acc[i] = 0.f;

    int beg = d_indptr[node], end = d_indptr[node + 1];
    int e = beg;

    for (; e + 2 < end; e += 3) {
        int s0 = d_csrc[e], s1 = d_csrc[e + 1], s2 = d_csrc[e + 2];
        float xv0[16], xv1[16], xv2[16];
        ld_xl16f(d_xl16 + (bb + s0) * HC + eoff, xv0);
        ld_xl16f(d_xl16 + (bb + s1) * HC + eoff, xv1);
        ld_xl16f(d_xl16 + (bb + s2) * HC + eoff, xv2);
        float p0 = 0.f, p1 = 0.f, p2 = 0.f;
        #pragma unroll
        for (int i = 0; i < 16; i++) {
            float e0 = xv0[i] + xrr[i]; e0 = fmaxf(e0, 0.2f * e0);
            float e1 = xv1[i] + xrr[i]; e1 = fmaxf(e1, 0.2f * e1);
            float e2 = xv2[i] + xrr[i]; e2 = fmaxf(e2, 0.2f * e2);
            p0 = fmaf(e0, attr[i], p0);
            p1 = fmaf(e1, attr[i], p1);
            p2 = fmaf(e2, attr[i], p2);
        }
        #pragma unroll
        for (int off = 4; off > 0; off >>= 1) {
            p0 += __shfl_xor_sync(0xffffffffu, p0, off);
            p1 += __shfl_xor_sync(0xffffffffu, p1, off);
            p2 += __shfl_xor_sync(0xffffffffu, p2, off);
        }
        float nm = fmaxf(fmaxf(m, p0), fmaxf(p1, p2));
        float sc = __expf(m - nm);
        float w0 = __expf(p0 - nm);
        float w1 = __expf(p1 - nm);
        float w2 = __expf(p2 - nm);
        s = fmaf(s, sc, w0 + w1 + w2);
        #pragma unroll
        for (int i = 0; i < 16; i++)
            acc[i] = fmaf(acc[i], sc,
                          fmaf(w0, xv0[i], fmaf(w1, xv1[i], w2 * xv2[i])));
        m = nm;
    }
    for (; e < end; e++) {
        int s0 = d_csrc[e];
        float xv0[16];
        ld_xl16f(d_xl16 + (bb + s0) * HC + eoff, xv0);
        float p0 = 0.f;
        #pragma unroll
        for (int i = 0; i < 16; i++) {
            float e0 = xv0[i] + xrr[i]; e0 = fmaxf(e0, 0.2f * e0);
            p0 = fmaf(e0, attr[i], p0);
        }
        #pragma unroll
        for (int off = 4; off > 0; off >>= 1)
            p0 += __shfl_xor_sync(0xffffffffu, p0, off);
        float nm = fmaxf(m, p0);
        float sc = __expf(m - nm);
        float w0 = __expf(p0 - nm);
        s = fmaf(s, sc, w0);
        #pragma unroll
        for (int i = 0; i < 16; i++)
            acc[i] = fmaf(acc[i], sc, w0 * xv0[i]);
        m = nm;
    }

    float r = 0.25f / s;
    float o[16];
    #pragma unroll
    for (int i = 0; i < 16; i++) {
        float v = acc[i] * r;
        v += __shfl_xor_sync(0xffffffffu, v, 8);
        v += __shfl_xor_sync(0xffffffffu, v, 16);
        o[i] = v;
    }

    if (h == 0) {
        size_t base = (bb + node) * CH + l8 * 16;
        #pragma unroll
        for (int q = 0; q < 4; q++) {
            float4 gv = *(const float4*)(gat_bias + l8 * 16 + q * 4);
            float4 v;
            v.x = o[q * 4 + 0] + gv.x;
            v.y = o[q * 4 + 1] + gv.y;
            v.z = o[q * 4 + 2] + gv.z;
            v.w = o[q * 4 + 3] + gv.w;
            cvt_store(d_hhi, d_hlo, base + q * 4, v);
        }
    }
}

// ---------------- GEMM 2 via HMMA: out = relu(h @ fc_w^T + fc_b) -------------
#define KPB   144
#define FC_A   0
#define FC_AL  (128 * KPB)
#define FC_B   (2 * 128 * KPB)
#define FC_BL  (3 * 128 * KPB)
#define SMEM_FC (4 * 128 * KPB)   // 73728

__global__ void __launch_bounds__(256) gemm_fc_mma(
    const float* __restrict__ bias, float* __restrict__ out,
    int row_base, int row_limit)
{
    extern __shared__ char smem[];
    const uint32_t sbase = smem_u32(smem);
    const int tid  = threadIdx.x;
    const int wid  = tid >> 5;
    const int lane = tid & 31;
    const int warp_m = wid & 3;
    const int warp_n = wid >> 2;
    const int row0 = row_base + blockIdx.x * 128;

    float acc[2][8][4];
    #pragma unroll
    for (int i = 0; i < 2; i++)
        #pragma unroll
        for (int j = 0; j < 8; j++)
            #pragma unroll
            for (int q = 0; q < 4; q++) acc[i][j][q] = 0.f;

    const int a_row  = warp_m * 32 + (lane & 15);
    const int a_koff = (lane >> 4) * 16;
    const int b_row  = warp_n * 64 + (lane >> 4) * 8 + (lane & 7);
    const int b_koff = ((lane >> 3) & 1) * 16;

    #pragma unroll 1
    for (int c = 0; c < 2; c++) {
        const int k0 = c * 64;
        #pragma unroll
        for (int i = 0; i < 4; i++) {
            int idx = i * 256 + tid;
            int r = idx >> 3, g = idx & 7;
            uint32_t soff = (uint32_t)(r * KPB + g * 16);
            int grow = row0 + r; if (grow >= row_limit) grow = row_limit - 1;
            size_t aoff = (size_t)grow * CH + k0 + g * 8;
            size_t boff = (size_t)r * CH + k0 + g * 8;
            CP_ASYNC16(sbase + FC_A  + soff, d_hhi  + aoff);
            CP_ASYNC16(sbase + FC_AL + soff, d_hlo  + aoff);
            CP_ASYNC16(sbase + FC_B  + soff, d_fwhi + boff);
            CP_ASYNC16(sbase + FC_BL + soff, d_fwlo + boff);
        }
        CP_COMMIT();
        CP_WAIT(0);
        __syncthreads();

        #pragma unroll
        for (int ks = 0; ks < 4; ks++) {
            const int kb = ks * 32;
            uint32_t ahi[2][4], alo[2][4], bhi[8][2], blo[8][2];
            #pragma unroll
            for (int mi = 0; mi < 2; mi++) {
                uint32_t ao = sbase + (uint32_t)((a_row + mi * 16) * KPB + a_koff + kb);
                LDSM_X4(ahi[mi][0], ahi[mi][1], ahi[mi][2], ahi[mi][3], ao + FC_A);
                LDSM_X4(alo[mi][0], alo[mi][1], alo[mi][2], alo[mi][3], ao + FC_AL);
            }
            #pragma unroll
            for (int p = 0; p < 4; p++) {
                uint32_t bo = sbase + (uint32_t)((b_row + p * 16) * KPB + b_koff + kb);
                uint32_t t0, t1, t2, t3;
                LDSM_X4(t0, t1, t2, t3, bo + FC_B);
                bhi[2 * p][0] = t0; bhi[2 * p][1] = t1;
                bhi[2 * p + 1][0] = t2; bhi[2 * p + 1][1] = t3;
                LDSM_X4(t0, t1, t2, t3, bo + FC_BL);
                blo[2 * p][0] = t0; blo[2 * p][1] = t1;
                blo[2 * p + 1][0] = t2; blo[2 * p + 1][1] = t3;
            }
            #pragma unroll
            for (int mi = 0; mi < 2; mi++)
                #pragma unroll
                for (int ni = 0; ni < 8; ni++) {
                    MMA_BF16(acc[mi][ni], ahi[mi], bhi[ni]);
                    MMA_BF16(acc[mi][ni], ahi[mi], blo[ni]);
                    MMA_BF16(acc[mi][ni], alo[mi], bhi[ni]);
                }
        }
        __syncthreads();
    }

    const int wcolbase = warp_n * 64;
    const int lrow = lane >> 2;
    const int lcol = (lane & 3) * 2;
    #pragma unroll
    for (int mi = 0; mi < 2; mi++) {
        int gr0 = row0 + warp_m * 32 + mi * 16 + lrow;
        #pragma unroll
        for (int ni = 0; ni < 8; ni++) {
            int wc = wcolbase + ni * 8 + lcol;
            float b0 = bias[wc], b1 = bias[wc + 1];
            if (gr0 < row_limit) {
                float2 v = {fmaxf(acc[mi][ni][0] + b0, 0.f),
                            fmaxf(acc[mi][ni][1] + b1, 0.f)};
                *(float2*)(out + (size_t)gr0 * CH + wc) = v;
            }
            if (gr0 + 8 < row_limit) {
                float2 v = {fmaxf(acc[mi][ni][2] + b0, 0.f),
                            fmaxf(acc[mi][ni][3] + b1, 0.f)};
                *(float2*)(out + (size_t)(gr0 + 8) * CH + wc) = v;
            }
        }
    }
}

// ---------------- launch -----------------------------------------------------
extern "C" void kernel_launch(void* const* d_in, const int* in_sizes, int n_in,
                              void* d_out, int out_size)
{
    const float* x   = (const float*)d_in[0];
    const void*  ei  = d_in[1];
    const float* Wl  = (const float*)d_in[2];
    const float* bl  = (const float*)d_in[3];
    const float* Wr  = (const float*)d_in[4];
    const float* br  = (const float*)d_in[5];
    const float* att = (const float*)d_in[6];
    const float* gb  = (const float*)d_in[7];
    const float* fcw = (const float*)d_in[8];
    const float* fcb = (const float*)d_in[9];

    static int configured = 0;
    static cudaStream_t s_side;
    static cudaEvent_t ev_fork, ev_csr, ev_g0, ev_fc01;
    if (!configured) {
        cudaFuncSetAttribute(gemm_xlr_mma,
                             cudaFuncAttributeMaxDynamicSharedMemorySize, SMEM_G1);
        cudaFuncSetAttribute(gemm_fc_mma,
                             cudaFuncAttributeMaxDynamicSharedMemorySize, SMEM_FC);
        cudaStreamCreateWithFlags(&s_side, cudaStreamNonBlocking);
        cudaEventCreateWithFlags(&ev_fork, cudaEventDisableTiming);
        cudaEventCreateWithFlags(&ev_csr, cudaEventDisableTiming);
        cudaEventCreateWithFlags(&ev_g0, cudaEventDisableTiming);
        cudaEventCreateWithFlags(&ev_fc01, cudaEventDisableTiming);
        configured = 1;
    }

    const int HALF_ROWS = ROWS_TOT / 2;             // 20000 (batches 0,1 / 2,3)
    const int GX_HALF   = (HALF_ROWS + 127) / 128;  // 157

    // fork: CSR chain on side stream
    cudaEventRecord(ev_fork, 0);
    cudaStreamWaitEvent(s_side, ev_fork, 0);
    count_kernel<<<(E_EDGES + 255) / 256, 256, 0, s_side>>>(ei);
    scan_kernel<<<1, 1024, 0, s_side>>>();
    fill_kernel<<<(E_TOT + 255) / 256, 256, 0, s_side>>>(ei);
    cudaEventRecord(ev_csr, s_side);

    // main: convert + gemm1 half 0 (batches 0,1)
    const int cvt_tot = XN4 + 2 * WN4H + FW4;
    convert_kernel<<<(cvt_tot + 255) / 256, 256>>>(x, Wl, Wr, fcw);
    gemm_xlr_mma<<<dim3(GX_HALF, 8), 256, SMEM_G1>>>(bl, br, 0, HALF_ROWS);
    cudaEventRecord(ev_g0, 0);

    // main: gemm1 half 1 (batches 2,3)
    gemm_xlr_mma<<<dim3(GX_HALF, 8), 256, SMEM_G1>>>(bl, br, HALF_ROWS, ROWS_TOT);

    // side: gat batches 0,1 (after gemm half0 + CSR, which is already ordered
    // on this stream), then fc rows 0..HALF overlapped with main's gat 2,3
    cudaStreamWaitEvent(s_side, ev_g0, 0);
    gat_edge_kernel<<<dim3(N_NODES / 8, 2), 256, 0, s_side>>>(att, gb, 0);
    gemm_fc_mma<<<GX_HALF, 256, SMEM_FC, s_side>>>(fcb, (float*)d_out, 0, HALF_ROWS);
    cudaEventRecord(ev_fc01, s_side);

    // main: gat batches 2,3 (after CSR), fc rows HALF..TOT, join fc01
    cudaStreamWaitEvent(0, ev_csr, 0);
    gat_edge_kernel<<<dim3(N_NODES / 8, 2), 256>>>(att, gb, 2);
    gemm_fc_mma<<<GX_HALF, 256, SMEM_FC>>>(fcb, (float*)d_out, HALF_ROWS, ROWS_TOT);
    cudaStreamWaitEvent(0, ev_fc01, 0);
}